// round 12
// baseline (speedup 1.0000x reference)
#include <cuda_runtime.h>
#include <cuda_bf16.h>
#include <math.h>

#define Bb 4
#define Nn 256
#define Dd 128
#define NODES (Bb*Nn)
#define MAXN (1.0f - 4e-3f)
#define NSLICE 8   // j-slices (Nn/32)

// ---------------- scratch (__device__ globals; allocation-free) ----------------
__device__ float g_h[NODES*Dd];
__device__ float g_s[NODES];
__device__ float g_r[NODES*Dd];
__device__ float g_sup[NODES*NSLICE];         // per-slice sums of w_ij * U_ij
__device__ float g_part[NSLICE*NODES*Dd];     // per-slice partials of (wV) @ H  (4 MB)

__device__ __forceinline__ float artanhf_c(float x) {
    x = fminf(fmaxf(x, -1.0f + 1e-7f), 1.0f - 1e-7f);
    return 0.5f * logf((1.0f + x) / (1.0f - x));
}

__device__ __forceinline__ float tanhap(float x) {
    float y;
    asm("tanh.approx.f32 %0, %1;" : "=f"(y) : "f"(x));
    return y;
}

__device__ __forceinline__ float dot4(float4 a, float4 b) {
    return fmaf(a.x, b.x, fmaf(a.y, b.y, fmaf(a.z, b.z, a.w * b.w)));
}

__device__ __forceinline__ float warpSum(float v) {
    #pragma unroll
    for (int o = 16; o > 0; o >>= 1) v += __shfl_xor_sync(0xffffffffu, v, o);
    return v;
}

__device__ __forceinline__ void stageW(float4* Ws4, const float* __restrict__ src,
                                       int rstride4, int coff4, int t, int nthreads) {
    const float4* s4 = (const float4*)src;
    for (int idx = t; idx < 4096; idx += nthreads) {
        int c = idx >> 5, m4 = idx & 31;
        Ws4[c*33 + m4] = s4[c*rstride4 + coff4 + m4];
    }
}

__device__ __forceinline__ void matvecP(const float4* __restrict__ Ws4,
                                        const float4* __restrict__ v, int lane,
                                        float out[4]) {
    float a0 = 0.f, a1 = 0.f, a2 = 0.f, a3 = 0.f;
    float b0 = 0.f, b1 = 0.f, b2 = 0.f, b3 = 0.f;
    const float4* w0p = Ws4 + lane*33;
    const float4* w1p = Ws4 + (lane+32)*33;
    const float4* w2p = Ws4 + (lane+64)*33;
    const float4* w3p = Ws4 + (lane+96)*33;
    #pragma unroll
    for (int m4 = 0; m4 < 32; m4 += 2) {
        float4 vm = v[m4];
        a0 += dot4(w0p[m4], vm);
        a1 += dot4(w1p[m4], vm);
        a2 += dot4(w2p[m4], vm);
        a3 += dot4(w3p[m4], vm);
        float4 vn = v[m4+1];
        b0 += dot4(w0p[m4+1], vn);
        b1 += dot4(w1p[m4+1], vn);
        b2 += dot4(w2p[m4+1], vn);
        b3 += dot4(w3p[m4+1], vn);
    }
    out[0] = a0 + b0; out[1] = a1 + b1; out[2] = a2 + b2; out[3] = a3 + b3;
}

// ======================= K1: HypLinear + R = H @ W1b^T (R10 config) =======================
__global__ void __launch_bounds__(128, 1)
k1_hyplinear(const float* __restrict__ x, const float* __restrict__ W,
             const float* __restrict__ b_lin, const float* __restrict__ att_w1) {
    extern __shared__ float4 dsm4[];
    float4* Ws4 = dsm4;            // 128*33
    float4* vs4 = dsm4 + 128*33;   // 4*32
    int t = threadIdx.x, wid = t >> 5, lane = t & 31;

    stageW(Ws4, W, 32, 0, t, 128);

    float bk[4];
    #pragma unroll
    for (int k = 0; k < 4; k++) bk[k] = b_lin[lane + 32*k];
    float bn2 = warpSum(bk[0]*bk[0] + bk[1]*bk[1] + bk[2]*bk[2] + bk[3]*bk[3]);
    float bn  = fmaxf(sqrtf(bn2), 1e-15f);
    float tb  = tanhf(bn);
    float hb[4];
    #pragma unroll
    for (int k = 0; k < 4; k++) hb[k] = tb * bk[k] / bn;
    float hbn = fabsf(tb);
    if (hbn > MAXN) { float s = MAXN/hbn;
        #pragma unroll
        for (int k = 0; k < 4; k++) hb[k] *= s; }
    float y2 = (hbn > MAXN) ? MAXN*MAXN : hbn*hbn;
    __syncthreads();

    int node = blockIdx.x * 4 + wid;
    float4* vw = vs4 + wid*32;
    float* vwf = (float*)vw;

    float4 x4 = ((const float4*)(x + node*Dd))[lane];
    vw[lane] = x4;
    __syncwarp();
    float xn2 = warpSum(dot4(x4, x4));
    float mx[4];
    matvecP(Ws4, vw, lane, mx);
    float mxn2 = warpSum(mx[0]*mx[0] + mx[1]*mx[1] + mx[2]*mx[2] + mx[3]*mx[3]);
    float res[4]; float rn;
    if (mxn2 == 0.0f) {
        res[0]=res[1]=res[2]=res[3]=0.f; rn = 0.0f;
    } else {
        float xn  = fmaxf(sqrtf(xn2), 1e-15f);
        float mxn = fmaxf(sqrtf(mxn2), 1e-15f);
        float arg = mxn / xn * artanhf_c(xn);
        float tt  = tanhf(arg);
        float sc  = tt / mxn;
        #pragma unroll
        for (int k = 0; k < 4; k++) res[k] = sc * mx[k];
        rn = fabsf(tt);
    }
    float rnc = fmaxf(rn, 1e-15f);
    if (rnc > MAXN) { float s = MAXN/rnc;
        #pragma unroll
        for (int k = 0; k < 4; k++) res[k] *= s; }
    float x2 = (rnc > MAXN) ? MAXN*MAXN : rn*rn;
    float xy = warpSum(res[0]*hb[0] + res[1]*hb[1] + res[2]*hb[2] + res[3]*hb[3]);
    float A  = 1.0f + 2.0f*xy + y2;
    float Bc = 1.0f - x2;
    float den = fmaxf(1.0f + 2.0f*xy + x2*y2, 1e-15f);
    float id = 1.0f/den;
    float h[4];
    #pragma unroll
    for (int k = 0; k < 4; k++) h[k] = (A*res[k] + Bc*hb[k]) * id;
    float hn2 = warpSum(h[0]*h[0] + h[1]*h[1] + h[2]*h[2] + h[3]*h[3]);
    float hn  = fmaxf(sqrtf(hn2), 1e-15f);
    float hs2;
    if (hn > MAXN) { float s = MAXN/hn;
        #pragma unroll
        for (int k = 0; k < 4; k++) h[k] *= s;
        hs2 = MAXN*MAXN; }
    else hs2 = hn2;
    #pragma unroll
    for (int k = 0; k < 4; k++) g_h[node*Dd + lane + 32*k] = h[k];
    if (lane == 0) g_s[node] = hs2;

    __syncthreads();
    stageW(Ws4, att_w1, 64, 32, t, 128);
    #pragma unroll
    for (int k = 0; k < 4; k++) vwf[lane + 32*k] = h[k];
    __syncthreads();
    float r[4];
    matvecP(Ws4, vw, lane, r);
    #pragma unroll
    for (int k = 0; k < 4; k++) g_r[node*Dd + lane + 32*k] = r[k];
}

// ======================= K3: pairwise attention, 32x32 tile, 2x2 register blocking =======================
// grid (Nn/32, Nn/32, Bb) = (8,8,4); 256 threads; thread covers i in {ti2, ti2+16}, j in {tj2, tj2+16}.
__global__ void __launch_bounds__(256)
k_pair(const float* __restrict__ mask, const float* __restrict__ att_b1,
       const float* __restrict__ att_w2, const float* __restrict__ att_b2) {
    extern __shared__ float4 psm4[];
    float4* hi4 = psm4;               // 32*33
    float4* hj4 = hi4 + 32*33;
    float4* ri4 = hj4 + 32*33;
    float4* rj4 = ri4 + 32*33;
    float4* w2s4 = rj4 + 32*33;       // 32
    float4* b1s4 = w2s4 + 32;         // 32
    float* fbase = (float*)(b1s4 + 32);
    float* ssi = fbase;               // 32
    float* ssj = ssi + 32;            // 32
    float* redU = ssj + 32;           // 32*33
    float* redV = redU + 32*33;       // 32*33

    int b   = blockIdx.z;
    int slc = blockIdx.x;             // j-slice 0..7
    int i0  = blockIdx.y * 32;
    int j0  = slc * 32;
    int base = b * Nn;
    int tid = threadIdx.x;
    int ti2 = tid >> 4, tj2 = tid & 15;

    for (int idx = tid; idx < 32*32; idx += 256) {
        int row = idx >> 5, k4 = idx & 31;
        hi4[row*33 + k4] = ((const float4*)(g_h + (base + i0 + row)*Dd))[k4];
        hj4[row*33 + k4] = ((const float4*)(g_h + (base + j0 + row)*Dd))[k4];
        ri4[row*33 + k4] = ((const float4*)(g_r + (base + i0 + row)*Dd))[k4];
        rj4[row*33 + k4] = ((const float4*)(g_r + (base + j0 + row)*Dd))[k4];
    }
    if (tid < 32) ssi[tid] = g_s[base + i0 + tid];
    else if (tid < 64) ssj[tid-32] = g_s[base + j0 + (tid-32)];
    else if (tid < 96) w2s4[tid-64] = ((const float4*)att_w2)[tid-64];
    else if (tid < 128) {
        float4 bv = ((const float4*)att_b1)[tid-96];     // b1/2 for halved silu
        b1s4[tid-96] = make_float4(0.5f*bv.x, 0.5f*bv.y, 0.5f*bv.z, 0.5f*bv.w);
    }
    float m00 = mask[(base + i0 + ti2)*Nn + j0 + tj2];
    float m01 = mask[(base + i0 + ti2)*Nn + j0 + tj2 + 16];
    float m10 = mask[(base + i0 + ti2 + 16)*Nn + j0 + tj2];
    float m11 = mask[(base + i0 + ti2 + 16)*Nn + j0 + tj2 + 16];
    float b2v = __ldg(att_b2);
    __syncthreads();

    // 2x2 gram
    float g00=0.f, g01=0.f, g10=0.f, g11=0.f;
    #pragma unroll
    for (int k4 = 0; k4 < 32; k4++) {
        float4 iA = hi4[ti2*33 + k4];
        float4 iB = hi4[(ti2+16)*33 + k4];
        float4 jA = hj4[tj2*33 + k4];
        float4 jB = hj4[(tj2+16)*33 + k4];
        g00 += dot4(iA, jA); g01 += dot4(iA, jB);
        g10 += dot4(iB, jA); g11 += dot4(iB, jB);
    }
    float siA = ssi[ti2], siB = ssi[ti2+16];
    float sjA = ssj[tj2], sjB = ssj[tj2+16];

    float U[2][2], V[2][2], U2[2][2], V2[2][2];
    #pragma unroll
    for (int pi = 0; pi < 2; pi++) {
        float si = pi ? siB : siA;
        #pragma unroll
        for (int pj = 0; pj < 2; pj++) {
            float sj = pj ? sjB : sjA;
            float g  = pi ? (pj ? g11 : g10) : (pj ? g01 : g00);
            float A   = 1.0f - 2.0f*g + sj;
            float Bc  = 1.0f - si;
            float den = fmaxf(1.0f - 2.0f*g + si*sj, 1e-15f);
            float p = -A / den, q = Bc / den;
            float sn2 = fmaf(p*p, si, fmaf(2.0f*p*q, g, q*q*sj));
            float sn  = fmaxf(sqrtf(fmaxf(sn2, 0.0f)), 1e-15f);
            float fac = fmaxf(1.0f - si, 1e-15f) * artanhf_c(sn) / sn;
            U[pi][pj] = fac * p; V[pi][pj] = fac * q;
            U2[pi][pj] = 0.5f * U[pi][pj]; V2[pi][pj] = 0.5f * V[pi][pj];
        }
    }

    // attention logits for 4 pairs; silu(a) = fmaf(a2, tanh(a2), a2), a2 = a/2
    float e00=0.f, e01=0.f, e10=0.f, e11=0.f;
    #pragma unroll
    for (int k4 = 0; k4 < 32; k4++) {
        float4 rA = ri4[ti2*33 + k4];
        float4 rB = ri4[(ti2+16)*33 + k4];
        float4 sA = rj4[tj2*33 + k4];
        float4 sB = rj4[(tj2+16)*33 + k4];
        float4 bv = b1s4[k4];
        float4 wv = w2s4[k4];
        #pragma unroll
        for (int el = 0; el < 4; el++) {
            float riA = (&rA.x)[el], riB = (&rB.x)[el];
            float rjA = (&sA.x)[el], rjB = (&sB.x)[el];
            float bb = (&bv.x)[el], ww = (&wv.x)[el];
            float a2, s;
            a2 = fmaf(U2[0][0], riA, fmaf(V2[0][0], rjA, bb));
            s = fmaf(a2, tanhap(a2), a2); e00 = fmaf(ww, s, e00);
            a2 = fmaf(U2[0][1], riA, fmaf(V2[0][1], rjB, bb));
            s = fmaf(a2, tanhap(a2), a2); e01 = fmaf(ww, s, e01);
            a2 = fmaf(U2[1][0], riB, fmaf(V2[1][0], rjA, bb));
            s = fmaf(a2, tanhap(a2), a2); e10 = fmaf(ww, s, e10);
            a2 = fmaf(U2[1][1], riB, fmaf(V2[1][1], rjB, bb));
            s = fmaf(a2, tanhap(a2), a2); e11 = fmaf(ww, s, e11);
        }
    }
    float w00 = __fdividef(1.0f, 1.0f + __expf(-(e00 + b2v))) * m00;
    float w01 = __fdividef(1.0f, 1.0f + __expf(-(e01 + b2v))) * m01;
    float w10 = __fdividef(1.0f, 1.0f + __expf(-(e10 + b2v))) * m10;
    float w11 = __fdividef(1.0f, 1.0f + __expf(-(e11 + b2v))) * m11;

    redU[ti2*33 + tj2]           = w00 * U[0][0];
    redU[ti2*33 + tj2 + 16]      = w01 * U[0][1];
    redU[(ti2+16)*33 + tj2]      = w10 * U[1][0];
    redU[(ti2+16)*33 + tj2 + 16] = w11 * U[1][1];
    redV[ti2*33 + tj2]           = w00 * V[0][0];
    redV[ti2*33 + tj2 + 16]      = w01 * V[0][1];
    redV[(ti2+16)*33 + tj2]      = w10 * V[1][0];
    redV[(ti2+16)*33 + tj2 + 16] = w11 * V[1][1];
    __syncthreads();

    // sup: rows ti2 and ti2+16 summed over 32 j (ascending, deterministic)
    if (tj2 == 0) {
        #pragma unroll
        for (int rr = 0; rr < 2; rr++) {
            int row = ti2 + 16*rr;
            float s = 0.f;
            #pragma unroll
            for (int jj = 0; jj < 32; jj++) s += redU[row*33 + jj];
            g_sup[(base + i0 + row)*NSLICE + slc] = s;
        }
    }

    // aggregation: part[i][c] = sum_{j=0..31} (wV)[i][j] * h_j[c]
    // thread: i-row a = tid>>3; channel float4 positions {cg, cg+8, cg+16, cg+24}, cg = tid&7
    int a  = tid >> 3;
    int cg = tid & 7;
    float4 acc[4];
    #pragma unroll
    for (int s = 0; s < 4; s++) acc[s] = make_float4(0.f,0.f,0.f,0.f);
    #pragma unroll 8
    for (int j = 0; j < 32; j++) {
        float m = redV[a*33 + j];
        #pragma unroll
        for (int s = 0; s < 4; s++) {
            float4 hv = hj4[j*33 + cg + 8*s];
            acc[s].x = fmaf(m, hv.x, acc[s].x);
            acc[s].y = fmaf(m, hv.y, acc[s].y);
            acc[s].z = fmaf(m, hv.z, acc[s].z);
            acc[s].w = fmaf(m, hv.w, acc[s].w);
        }
    }
    float4* gp = (float4*)(g_part + ((size_t)slc*NODES + base + i0 + a)*Dd);
    #pragma unroll
    for (int s = 0; s < 4; s++) gp[cg + 8*s] = acc[s];
}

// ======================= K5: combine + node MLP + expmap + HypAct (R10 config) =======================
__global__ void __launch_bounds__(128, 1)
k5_mlp(const float* __restrict__ mlp_w1, const float* __restrict__ mlp_b1,
       const float* __restrict__ mlp_w2, const float* __restrict__ mlp_b2,
       float* __restrict__ out) {
    extern __shared__ float4 dsm4[];
    float4* Ws4 = dsm4;
    float4* vs4 = dsm4 + 128*33;
    int t = threadIdx.x, wid = t >> 5, lane = t & 31;

    stageW(Ws4, mlp_w1, 64, 32, t, 128);
    __syncthreads();

    int node = blockIdx.x * 4 + wid;
    float4* vw = vs4 + wid*32;
    float* vwf = (float*)vw;

    float4 sv = make_float4(0.f,0.f,0.f,0.f);
    #pragma unroll
    for (int jt = 0; jt < NSLICE; jt++) {
        float4 pv = ((const float4*)(g_part + ((size_t)jt*NODES + node)*Dd))[lane];
        sv.x += pv.x; sv.y += pv.y; sv.z += pv.z; sv.w += pv.w;
    }
    float su = 0.f;
    #pragma unroll
    for (int jt = 0; jt < NSLICE; jt++) su += g_sup[node*NSLICE + jt];
    float4 h4 = ((const float4*)(g_h + node*Dd))[lane];
    vw[lane] = make_float4(fmaf(su, h4.x, sv.x), fmaf(su, h4.y, sv.y),
                           fmaf(su, h4.z, sv.z), fmaf(su, h4.w, sv.w));
    __syncwarp();
    float a[4];
    matvecP(Ws4, vw, lane, a);
    float sa[4];
    #pragma unroll
    for (int k = 0; k < 4; k++) {
        float av = a[k] + mlp_b1[lane + 32*k];
        sa[k] = av / (1.0f + __expf(-av));
    }

    __syncthreads();
    stageW(Ws4, mlp_w2, 32, 0, t, 128);
    #pragma unroll
    for (int k = 0; k < 4; k++) vwf[lane + 32*k] = sa[k];
    __syncthreads();
    float o[4];
    matvecP(Ws4, vw, lane, o);
    float h[4];
    #pragma unroll
    for (int k = 0; k < 4; k++) {
        o[k] += mlp_b2[lane + 32*k];
        h[k] = g_h[node*Dd + lane + 32*k];
    }

    float si = g_s[node];
    float un2 = warpSum(o[0]*o[0] + o[1]*o[1] + o[2]*o[2] + o[3]*o[3]);
    float un  = fmaxf(sqrtf(un2), 1e-15f);
    float lam = 2.0f / fmaxf(1.0f - si, 1e-15f);
    float tt  = tanhf(0.5f * lam * un);
    float sc  = tt / un;
    float sec[4];
    #pragma unroll
    for (int k = 0; k < 4; k++) sec[k] = sc * o[k];
    float y2  = tt * tt;
    float xy = warpSum(h[0]*sec[0] + h[1]*sec[1] + h[2]*sec[2] + h[3]*sec[3]);
    float A   = 1.0f + 2.0f*xy + y2;
    float Bc  = 1.0f - si;
    float den = fmaxf(1.0f + 2.0f*xy + si*y2, 1e-15f);
    float id  = 1.0f/den;
    float ov[4];
    #pragma unroll
    for (int k = 0; k < 4; k++) ov[k] = (A*h[k] + Bc*sec[k]) * id;
    float on2 = warpSum(ov[0]*ov[0] + ov[1]*ov[1] + ov[2]*ov[2] + ov[3]*ov[3]);
    float on  = fmaxf(sqrtf(on2), 1e-15f);
    float pn2;
    if (on > MAXN) { float s = MAXN/on;
        #pragma unroll
        for (int k = 0; k < 4; k++) ov[k] *= s;
        pn2 = MAXN*MAXN; }
    else pn2 = on2;
    float pn  = fmaxf(sqrtf(pn2), 1e-15f);
    float lsc = artanhf_c(pn) / pn;
    float xt[4];
    #pragma unroll
    for (int k = 0; k < 4; k++) {
        float v = lsc * ov[k];
        xt[k] = v / (1.0f + __expf(-v));
    }
    float un3 = warpSum(xt[0]*xt[0] + xt[1]*xt[1] + xt[2]*xt[2] + xt[3]*xt[3]);
    float u3n = fmaxf(sqrtf(un3), 1e-15f);
    float t3  = tanhf(u3n);
    float rsc = t3 / u3n;
    float rn  = fmaxf(fabsf(t3), 1e-15f);
    float fin = (rn > MAXN) ? rsc * (MAXN/rn) : rsc;
    #pragma unroll
    for (int k = 0; k < 4; k++) out[node*Dd + lane + 32*k] = fin * xt[k];
}

// ======================= launch =======================
extern "C" void kernel_launch(void* const* d_in, const int* in_sizes, int n_in,
                              void* d_out, int out_size) {
    const float* x      = (const float*)d_in[0];
    const float* mask   = (const float*)d_in[1];
    const float* W      = (const float*)d_in[2];
    const float* b_lin  = (const float*)d_in[3];
    const float* att_w1 = (const float*)d_in[4];
    const float* att_b1 = (const float*)d_in[5];
    const float* att_w2 = (const float*)d_in[6];
    const float* att_b2 = (const float*)d_in[7];
    const float* mlp_w1 = (const float*)d_in[8];
    const float* mlp_b1 = (const float*)d_in[9];
    const float* mlp_w2 = (const float*)d_in[10];
    const float* mlp_b2 = (const float*)d_in[11];
    float* out = (float*)d_out;

    const int smemW = (128*33 + 4*32) * (int)sizeof(float4);            // 69,632 B
    const int smemP = (4*32*33 + 64) * (int)sizeof(float4)
                    + (64 + 2*32*33) * (int)sizeof(float);              // 77,312 B
    cudaFuncSetAttribute(k1_hyplinear, cudaFuncAttributeMaxDynamicSharedMemorySize, smemW);
    cudaFuncSetAttribute(k_pair,       cudaFuncAttributeMaxDynamicSharedMemorySize, smemP);
    cudaFuncSetAttribute(k5_mlp,       cudaFuncAttributeMaxDynamicSharedMemorySize, smemW);

    k1_hyplinear<<<NODES/4, 128, smemW>>>(x, W, b_lin, att_w1);
    dim3 g3(Nn/32, Nn/32, Bb);
    k_pair<<<g3, 256, smemP>>>(mask, att_b1, att_w2, att_b2);
    k5_mlp<<<NODES/4, 128, smemW>>>(mlp_w1, mlp_b1, mlp_w2, mlp_b2, out);
}